// round 5
// baseline (speedup 1.0000x reference)
#include <cuda_runtime.h>
#include <cuda_bf16.h>
#include <math.h>
#include <stdint.h>

// Problem dims (fixed)
#define BB 4
#define SS 2048
#define DD 1024
#define MS (BB*SS)          // 8192 rows total
#define OUT_ELEMS (MS*DD)

// smem tile geometry: rows are 32 bf16 (64B) padded to 80B (conflict-free)
#define ROWB   80
#define ATILEB (256*ROWB)   // 20480 B (A operand, 256 rows)
#define BTILEB (128*ROWB)   // 10240 B (B operand, 128 rows)
#define STAGEB (2*ATILEB + 2*BTILEB)   // Ah, Al, Bh, Bl = 61440 B
#define NSTAGE 3
#define SMEMB  (NSTAGE*STAGEB)         // 184320 B

// ---------------------------------------------------------------------------
// PTX helpers (sm_80-level only: cp.async, ldmatrix, mma.sync bf16)
// ---------------------------------------------------------------------------
__device__ __forceinline__ uint32_t smem_u32(const void* p) {
    uint32_t a;
    asm("{ .reg .u64 t; cvta.to.shared.u64 t, %1; cvt.u32.u64 %0, t; }" : "=r"(a) : "l"(p));
    return a;
}
#define CP16(d, s) asm volatile("cp.async.cg.shared.global [%0], [%1], 16;" :: "r"(d), "l"(s))
#define CPCOMMIT() asm volatile("cp.async.commit_group;" ::: "memory")
#define CPWAIT(n)  asm volatile("cp.async.wait_group %0;" :: "n"(n) : "memory")

__device__ __forceinline__ void ldsm4(uint32_t* r, uint32_t a) {
    asm volatile("ldmatrix.sync.aligned.m8n8.x4.shared.b16 {%0,%1,%2,%3}, [%4];"
                 : "=r"(r[0]), "=r"(r[1]), "=r"(r[2]), "=r"(r[3]) : "r"(a));
}
__device__ __forceinline__ void mma16816(float* c, const uint32_t* a, const uint32_t* b) {
    asm volatile("mma.sync.aligned.m16n8k16.row.col.f32.bf16.bf16.f32 "
                 "{%0,%1,%2,%3}, {%4,%5,%6,%7}, {%8,%9}, {%0,%1,%2,%3};"
                 : "+f"(c[0]), "+f"(c[1]), "+f"(c[2]), "+f"(c[3])
                 : "r"(a[0]), "r"(a[1]), "r"(a[2]), "r"(a[3]), "r"(b[0]), "r"(b[1]));
}

// ---------------------------------------------------------------------------
// Static scratch (allocation-free rule)
// ---------------------------------------------------------------------------
__device__ __align__(256) __nv_bfloat16 g_xh[MS*DD], g_xl[MS*DD];
__device__ __align__(256) __nv_bfloat16 g_wth[3*DD*DD], g_wtl[3*DD*DD];   // W^T concat [3N,K]
__device__ __align__(256) __nv_bfloat16 g_qh[MS*DD], g_ql[MS*DD];
__device__ __align__(256) __nv_bfloat16 g_kh[MS*DD], g_kl[MS*DD];
__device__ __align__(256) __nv_bfloat16 g_vh[MS*DD], g_vl[MS*DD];
__device__ __align__(256) __nv_bfloat16 g_vth[(size_t)BB*DD*SS], g_vtl[(size_t)BB*DD*SS];
__device__ __align__(256) float          g_p[(size_t)BB*SS*SS];
__device__ __align__(256) __nv_bfloat16 g_ph[(size_t)BB*SS*SS], g_pl[(size_t)BB*SS*SS];
__device__ __align__(256) float          g_ent[MS];

// Epilogue routing for the fused QKV projection (3 outputs, select by column)
struct ProjOut {
    const float* bias[3];
    __nv_bfloat16* oh[3];
    __nv_bfloat16* ol[3];
};

// ---------------------------------------------------------------------------
// bf16 split GEMM via mma.sync:
//   C[M,N] = (Ah+Al)[M,K] x (Bh+Bl)[N,K]^T   (3 MMAs: hh + hl + lh)
// CTA tile 256x128, K-chunk 32, 512 threads = 16 warps (4 M x 4 N),
// warp tile 64x32, 3-stage cp.async pipeline, 1 CTA/SM.
// EPI 0: fp32 store. EPI 1: bf16 hi/lo split store routed via ProjOut.
// ---------------------------------------------------------------------------
template<int EPI>
__global__ __launch_bounds__(512, 1)
void mma_gemm(const __nv_bfloat16* __restrict__ Ah, const __nv_bfloat16* __restrict__ Al,
              const __nv_bfloat16* __restrict__ Bh, const __nv_bfloat16* __restrict__ Bl,
              float* __restrict__ Cf, ProjOut po,
              int N, int K, long sA, long sB, long sC)
{
    extern __shared__ char sm[];
    const uint32_t sb = smem_u32(sm);
    const int tid = threadIdx.x, lane = tid & 31, warp = tid >> 5;
    const int wm = warp & 3, wn = warp >> 2;     // 4 M-warps x 4 N-warps
    const int bz = blockIdx.z;

    const __nv_bfloat16* srcA[2] = {
        Ah + (long)bz * sA + (long)blockIdx.y * 256 * K,
        Al + (long)bz * sA + (long)blockIdx.y * 256 * K };
    const __nv_bfloat16* srcB[2] = {
        Bh + (long)bz * sB + (long)blockIdx.x * 128 * K,
        Bl + (long)bz * sB + (long)blockIdx.x * 128 * K };

    float acc[4][4][4];
    #pragma unroll
    for (int a = 0; a < 4; a++)
        #pragma unroll
        for (int b = 0; b < 4; b++)
            #pragma unroll
            for (int c = 0; c < 4; c++) acc[a][b][c] = 0.f;

    const int NC = K >> 5;

    // ---- g2s loader: A 256 rows + B 128 rows, 64B/row, 16B per cp.async ----
    const int lr = tid >> 2, lq = tid & 3;       // 128 rows per 512-thread pass
    auto load_stage = [&](int c) {
        const uint32_t dstS = sb + (uint32_t)(c % NSTAGE) * STAGEB;
        const long kof = (long)c * 32 + lq * 8;
        #pragma unroll
        for (int t = 0; t < 2; t++) {            // Ah, Al : 2 passes of 128 rows
            const uint32_t db = dstS + t * ATILEB + lr * ROWB + lq * 16;
            const __nv_bfloat16* s = srcA[t] + kof;
            CP16(db,               s + (long)lr * K);
            CP16(db + 128 * ROWB,  s + (long)(lr + 128) * K);
        }
        #pragma unroll
        for (int t = 0; t < 2; t++) {            // Bh, Bl : 1 pass of 128 rows
            CP16(dstS + 2 * ATILEB + t * BTILEB + lr * ROWB + lq * 16,
                 srcB[t] + (long)lr * K + kof);
        }
        CPCOMMIT();
    };

    load_stage(0);
    if (NC > 1) load_stage(1);
    if (NC > 2) load_stage(2);

    for (int c = 0; c < NC; c++) {
        if (c + 3 <= NC)      { CPWAIT(2); }
        else if (c + 2 == NC) { CPWAIT(1); }
        else                  { CPWAIT(0); }
        __syncthreads();

        const uint32_t stb = sb + (uint32_t)(c % NSTAGE) * STAGEB;
        #pragma unroll
        for (int ks = 0; ks < 2; ks++) {
            // A fragments (hi+lo): 4 m16 frags
            uint32_t aHi[4][4], aLo[4][4];
            const int rA   = wm * 64 + (lane & 15);
            const int colA = ks * 32 + ((lane >> 4) << 4);
            #pragma unroll
            for (int mf = 0; mf < 4; mf++) {
                const uint32_t ad = stb + (rA + mf * 16) * ROWB + colA;
                ldsm4(aHi[mf], ad);
                ldsm4(aLo[mf], ad + ATILEB);
            }
            // B in 2 groups of 16 rows (2 n8 frags each)
            const int rB   = wn * 32 + ((lane >> 4) & 1) * 8 + (lane & 7);
            const int colB = ks * 32 + ((lane >> 3) & 1) * 16;
            #pragma unroll
            for (int g = 0; g < 2; g++) {
                uint32_t bh4[4], bl4[4];
                const uint32_t bd = stb + 2 * ATILEB + (rB + g * 16) * ROWB + colB;
                ldsm4(bh4, bd);
                ldsm4(bl4, bd + BTILEB);
                #pragma unroll
                for (int mf = 0; mf < 4; mf++) {
                    mma16816(acc[mf][2*g],   aHi[mf], bh4);
                    mma16816(acc[mf][2*g],   aHi[mf], bl4);
                    mma16816(acc[mf][2*g],   aLo[mf], bh4);
                    mma16816(acc[mf][2*g+1], aHi[mf], bh4 + 2);
                    mma16816(acc[mf][2*g+1], aHi[mf], bl4 + 2);
                    mma16816(acc[mf][2*g+1], aLo[mf], bh4 + 2);
                }
            }
        }
        __syncthreads();
        if (c + 3 < NC) load_stage(c + 3);
    }

    // ---- epilogue ----
    const long rbase = (long)blockIdx.y * 256 + wm * 64 + (lane >> 2);
    const int  gcol0 = blockIdx.x * 128;

    if (EPI == 0) {
        #pragma unroll
        for (int mf = 0; mf < 4; mf++)
            #pragma unroll
            for (int rh = 0; rh < 2; rh++) {
                const long r = rbase + mf * 16 + rh * 8;
                #pragma unroll
                for (int nf = 0; nf < 4; nf++) {
                    const int col = gcol0 + wn * 32 + 2 * (lane & 3) + nf * 8;
                    float2 f2;
                    f2.x = acc[mf][nf][rh * 2 + 0];
                    f2.y = acc[mf][nf][rh * 2 + 1];
                    *(float2*)(Cf + (long)bz * sC + r * N + col) = f2;
                }
            }
    } else {
        // whole 128-col tile lives in one of q/k/v (N blocks of 1024)
        const int which = gcol0 >> 10;
        const int lcol0 = gcol0 & 1023;
        const float* bias = po.bias[which];
        __nv_bfloat16* Oh = po.oh[which];
        __nv_bfloat16* Ol = po.ol[which];
        #pragma unroll
        for (int mf = 0; mf < 4; mf++)
            #pragma unroll
            for (int rh = 0; rh < 2; rh++) {
                const long r = rbase + mf * 16 + rh * 8;
                #pragma unroll
                for (int nf = 0; nf < 4; nf++) {
                    const int col = lcol0 + wn * 32 + 2 * (lane & 3) + nf * 8;
                    float v0 = acc[mf][nf][rh * 2 + 0] + bias[col];
                    float v1 = acc[mf][nf][rh * 2 + 1] + bias[col + 1];
                    __nv_bfloat16 h0 = __float2bfloat16(v0);
                    __nv_bfloat16 h1 = __float2bfloat16(v1);
                    __nv_bfloat162 hh; hh.x = h0; hh.y = h1;
                    __nv_bfloat162 ll;
                    ll.x = __float2bfloat16(v0 - __bfloat162float(h0));
                    ll.y = __float2bfloat16(v1 - __bfloat162float(h1));
                    *(__nv_bfloat162*)(Oh + r * DD + col) = hh;
                    *(__nv_bfloat162*)(Ol + r * DD + col) = ll;
                }
            }
    }
}

// ---------------------------------------------------------------------------
// fp32 -> bf16 hi/lo elementwise split (float4 vectorized)
// ---------------------------------------------------------------------------
__global__ void split_kernel(const float* __restrict__ in, __nv_bfloat16* __restrict__ oh,
                             __nv_bfloat16* __restrict__ ol, int n4)
{
    int i = blockIdx.x * 256 + threadIdx.x;
    if (i < n4) {
        float4 v = ((const float4*)in)[i];
        __nv_bfloat16 h0 = __float2bfloat16(v.x), h1 = __float2bfloat16(v.y);
        __nv_bfloat16 h2 = __float2bfloat16(v.z), h3 = __float2bfloat16(v.w);
        __nv_bfloat162 hA; hA.x = h0; hA.y = h1;
        __nv_bfloat162 hB; hB.x = h2; hB.y = h3;
        __nv_bfloat162 lA, lB;
        lA.x = __float2bfloat16(v.x - __bfloat162float(h0));
        lA.y = __float2bfloat16(v.y - __bfloat162float(h1));
        lB.x = __float2bfloat16(v.z - __bfloat162float(h2));
        lB.y = __float2bfloat16(v.w - __bfloat162float(h3));
        ((__nv_bfloat162*)oh)[2*i]   = hA;
        ((__nv_bfloat162*)oh)[2*i+1] = hB;
        ((__nv_bfloat162*)ol)[2*i]   = lA;
        ((__nv_bfloat162*)ol)[2*i+1] = lB;
    }
}

// ---------------------------------------------------------------------------
// Transpose + split fp32 [R,C] -> bf16 hi/lo [C,R] (weights)
// ---------------------------------------------------------------------------
__global__ void transpose_split(const float* __restrict__ in, __nv_bfloat16* __restrict__ oh,
                                __nv_bfloat16* __restrict__ ol, int R, int C)
{
    __shared__ float t[32][33];
    const int c0 = blockIdx.x * 32, rr0 = blockIdx.y * 32;
    const int tx = threadIdx.x, ty = threadIdx.y;
    #pragma unroll
    for (int k = 0; k < 32; k += 8)
        t[ty + k][tx] = in[(long)(rr0 + ty + k) * C + c0 + tx];
    __syncthreads();
    #pragma unroll
    for (int k = 0; k < 32; k += 8) {
        float v = t[tx][ty + k];
        __nv_bfloat16 h = __float2bfloat16(v);
        long o = (long)(c0 + ty + k) * R + rr0 + tx;
        oh[o] = h;
        ol[o] = __float2bfloat16(v - __bfloat162float(h));
    }
}

// ---------------------------------------------------------------------------
// Batched bf16-pair transpose: [R,C] hi/lo -> [C,R] hi/lo (v -> v^T)
// ---------------------------------------------------------------------------
__global__ void transpose_pair(const __nv_bfloat16* __restrict__ ih, const __nv_bfloat16* __restrict__ il,
                               __nv_bfloat16* __restrict__ oh, __nv_bfloat16* __restrict__ ol,
                               int R, int C, long sIn, long sOut)
{
    __shared__ __nv_bfloat16 th[32][34], tl[32][34];
    ih += (long)blockIdx.z * sIn;  il += (long)blockIdx.z * sIn;
    oh += (long)blockIdx.z * sOut; ol += (long)blockIdx.z * sOut;
    const int c0 = blockIdx.x * 32, rr0 = blockIdx.y * 32;
    const int tx = threadIdx.x, ty = threadIdx.y;
    #pragma unroll
    for (int k = 0; k < 32; k += 8) {
        long i = (long)(rr0 + ty + k) * C + c0 + tx;
        th[ty + k][tx] = ih[i];
        tl[ty + k][tx] = il[i];
    }
    __syncthreads();
    #pragma unroll
    for (int k = 0; k < 32; k += 8) {
        long o = (long)(c0 + ty + k) * R + rr0 + tx;
        oh[o] = th[tx][ty + k];
        ol[o] = tl[tx][ty + k];
    }
}

// ---------------------------------------------------------------------------
// Row softmax + entropy; writes probs as bf16 hi/lo (PV GEMM A operand)
// ---------------------------------------------------------------------------
__global__ void softmax_ent(const float* __restrict__ P, __nv_bfloat16* __restrict__ Ph,
                            __nv_bfloat16* __restrict__ Pl, float* __restrict__ ent,
                            const float* __restrict__ temp)
{
    __shared__ float red[256];
    const float* p = P + (long)blockIdx.x * SS;
    __nv_bfloat16* oh = Ph + (long)blockIdx.x * SS;
    __nv_bfloat16* ol = Pl + (long)blockIdx.x * SS;
    const int tid = threadIdx.x;
    const float scale = 1.0f / (8.0f * temp[0]);

    float v[8];
    #pragma unroll
    for (int j = 0; j < 8; j++) v[j] = p[tid + j * 256] * scale;

    float m = v[0];
    #pragma unroll
    for (int j = 1; j < 8; j++) m = fmaxf(m, v[j]);
    red[tid] = m; __syncthreads();
    #pragma unroll
    for (int s = 128; s > 0; s >>= 1) {
        if (tid < s) red[tid] = fmaxf(red[tid], red[tid + s]);
        __syncthreads();
    }
    m = red[0]; __syncthreads();

    float e[8], l = 0.f, t = 0.f;
    #pragma unroll
    for (int j = 0; j < 8; j++) {
        e[j] = __expf(v[j] - m);
        l += e[j];
        t += e[j] * v[j];
    }
    red[tid] = l; __syncthreads();
    #pragma unroll
    for (int s = 128; s > 0; s >>= 1) {
        if (tid < s) red[tid] += red[tid + s];
        __syncthreads();
    }
    l = red[0]; __syncthreads();
    red[tid] = t; __syncthreads();
    #pragma unroll
    for (int s = 128; s > 0; s >>= 1) {
        if (tid < s) red[tid] += red[tid + s];
        __syncthreads();
    }
    t = red[0]; __syncthreads();

    const float inv = 1.0f / l;
    #pragma unroll
    for (int j = 0; j < 8; j++) {
        float pr = e[j] * inv;
        __nv_bfloat16 h = __float2bfloat16(pr);
        oh[tid + j * 256] = h;
        ol[tid + j * 256] = __float2bfloat16(pr - __bfloat162float(h));
    }
    if (tid == 0) ent[blockIdx.x] = m + logf(l) - t * inv;
}

__global__ void ent_reduce(const float* __restrict__ ent, float* __restrict__ out)
{
    __shared__ float red[256];
    const int tid = threadIdx.x;
    float s = 0.f;
    for (int i = tid; i < MS; i += 256) s += ent[i];
    red[tid] = s; __syncthreads();
    #pragma unroll
    for (int k = 128; k > 0; k >>= 1) {
        if (tid < k) red[tid] += red[tid + k];
        __syncthreads();
    }
    if (tid == 0) out[0] = red[0] / (float)MS;
}

// ---------------------------------------------------------------------------
extern "C" void kernel_launch(void* const* d_in, const int* in_sizes, int n_in,
                              void* d_out, int out_size)
{
    const float* x    = (const float*)d_in[0];
    const float* Wq   = (const float*)d_in[1];
    const float* bq   = (const float*)d_in[2];
    const float* Wk   = (const float*)d_in[3];
    const float* bk   = (const float*)d_in[4];
    const float* Wv   = (const float*)d_in[5];
    const float* bv   = (const float*)d_in[6];
    const float* temp = (const float*)d_in[7];
    float* out = (float*)d_out;

    __nv_bfloat16 *xh, *xl, *wth, *wtl, *qh, *ql, *kh, *kl, *vh, *vl, *vth, *vtl, *pph, *ppl;
    float *p, *ent;
    cudaGetSymbolAddress((void**)&xh,  g_xh);  cudaGetSymbolAddress((void**)&xl,  g_xl);
    cudaGetSymbolAddress((void**)&wth, g_wth); cudaGetSymbolAddress((void**)&wtl, g_wtl);
    cudaGetSymbolAddress((void**)&qh,  g_qh);  cudaGetSymbolAddress((void**)&ql,  g_ql);
    cudaGetSymbolAddress((void**)&kh,  g_kh);  cudaGetSymbolAddress((void**)&kl,  g_kl);
    cudaGetSymbolAddress((void**)&vh,  g_vh);  cudaGetSymbolAddress((void**)&vl,  g_vl);
    cudaGetSymbolAddress((void**)&vth, g_vth); cudaGetSymbolAddress((void**)&vtl, g_vtl);
    cudaGetSymbolAddress((void**)&p,   g_p);
    cudaGetSymbolAddress((void**)&pph, g_ph);  cudaGetSymbolAddress((void**)&ppl, g_pl);
    cudaGetSymbolAddress((void**)&ent, g_ent);

    cudaFuncSetAttribute(mma_gemm<0>, cudaFuncAttributeMaxDynamicSharedMemorySize, SMEMB);
    cudaFuncSetAttribute(mma_gemm<1>, cudaFuncAttributeMaxDynamicSharedMemorySize, SMEMB);

    ProjOut poNull = {};

    // 1) Split x; transpose+split weights into concat W^T [3*D, D]
    split_kernel<<<(MS*DD/4 + 255) / 256, 256>>>(x, xh, xl, MS*DD/4);
    {
        dim3 blk(32, 8);
        dim3 grd(DD / 32, DD / 32, 1);
        transpose_split<<<grd, blk>>>(Wq, wth + 0*DD*DD, wtl + 0*DD*DD, DD, DD);
        transpose_split<<<grd, blk>>>(Wk, wth + 1*DD*DD, wtl + 1*DD*DD, DD, DD);
        transpose_split<<<grd, blk>>>(Wv, wth + 2*DD*DD, wtl + 2*DD*DD, DD, DD);
    }
    // 2) Fused QKV projection: M=8192, N=3072, K=1024 -> bf16 hi/lo outputs
    {
        ProjOut po;
        po.bias[0] = bq; po.bias[1] = bk; po.bias[2] = bv;
        po.oh[0] = qh; po.oh[1] = kh; po.oh[2] = vh;
        po.ol[0] = ql; po.ol[1] = kl; po.ol[2] = vl;
        dim3 grd(3*DD / 128, MS / 256, 1);
        mma_gemm<1><<<grd, 512, SMEMB>>>(xh, xl, wth, wtl, nullptr, po, 3*DD, DD, 0, 0, 0);
    }
    // 3) v -> v^T hi/lo per batch ([S,D] -> [D,S])
    {
        dim3 blk(32, 8);
        dim3 grd(DD / 32, SS / 32, BB);
        transpose_pair<<<grd, blk>>>(vh, vl, vth, vtl, SS, DD, (long)SS * DD, (long)DD * SS);
    }
    // 4) Scores (per batch: 2048x2048, K=1024), unscaled fp32
    {
        dim3 grd(SS / 128, SS / 256, BB);
        mma_gemm<0><<<grd, 512, SMEMB>>>(qh, ql, kh, kl, p, poNull,
                                         SS, DD, (long)SS*DD, (long)SS*DD, (long)SS*SS);
    }
    // 5) Softmax + entropy; probs -> bf16 hi/lo
    softmax_ent<<<MS, 256>>>(p, pph, ppl, ent, temp);
    // 6) PV (per batch: 2048x1024, K=2048) -> out fp32
    {
        dim3 grd(DD / 128, SS / 256, BB);
        mma_gemm<0><<<grd, 512, SMEMB>>>(pph, ppl, vth, vtl, out, poNull,
                                         DD, SS, (long)SS*SS, (long)DD*SS, (long)SS*DD);
    }
    // 7) Entropy mean scalar
    ent_reduce<<<1, 256>>>(ent, out + OUT_ELEMS);
}

// round 6
// speedup vs baseline: 1.1547x; 1.1547x over previous
#include <cuda_runtime.h>
#include <cuda_bf16.h>
#include <math.h>
#include <stdint.h>

// Problem dims (fixed)
#define BB 4
#define SS 2048
#define DD 1024
#define MS (BB*SS)          // 8192 rows total
#define OUT_ELEMS (MS*DD)

// smem tile geometry: rows hold hi(64B) | lo(64B) packed, stride 144B
// (16B-aligned; 144B = 36 words -> bank step 4 per row, conflict-free ldmatrix)
#define ROWB   144
#define ATILEB (128*ROWB)   // 18432 B (A hi|lo packed)
#define BTILEB (128*ROWB)   // 18432 B (B hi|lo packed)
#define STAGEB (ATILEB + BTILEB)       // 36864 B
#define NSTAGE 3
#define SMEMB  (NSTAGE*STAGEB)         // 110592 B -> 2 CTAs/SM fits (221 KB)

// ---------------------------------------------------------------------------
// PTX helpers (sm_80-level only: cp.async, ldmatrix, mma.sync bf16)
// ---------------------------------------------------------------------------
__device__ __forceinline__ uint32_t smem_u32(const void* p) {
    uint32_t a;
    asm("{ .reg .u64 t; cvta.to.shared.u64 t, %1; cvt.u32.u64 %0, t; }" : "=r"(a) : "l"(p));
    return a;
}
#define CP16(d, s) asm volatile("cp.async.cg.shared.global [%0], [%1], 16;" :: "r"(d), "l"(s))
#define CPCOMMIT() asm volatile("cp.async.commit_group;" ::: "memory")
#define CPWAIT(n)  asm volatile("cp.async.wait_group %0;" :: "n"(n) : "memory")

__device__ __forceinline__ void ldsm4(uint32_t* r, uint32_t a) {
    asm volatile("ldmatrix.sync.aligned.m8n8.x4.shared.b16 {%0,%1,%2,%3}, [%4];"
                 : "=r"(r[0]), "=r"(r[1]), "=r"(r[2]), "=r"(r[3]) : "r"(a));
}
__device__ __forceinline__ void mma16816(float* c, const uint32_t* a, const uint32_t* b) {
    asm volatile("mma.sync.aligned.m16n8k16.row.col.f32.bf16.bf16.f32 "
                 "{%0,%1,%2,%3}, {%4,%5,%6,%7}, {%8,%9}, {%0,%1,%2,%3};"
                 : "+f"(c[0]), "+f"(c[1]), "+f"(c[2]), "+f"(c[3])
                 : "r"(a[0]), "r"(a[1]), "r"(a[2]), "r"(a[3]), "r"(b[0]), "r"(b[1]));
}

// ---------------------------------------------------------------------------
// Static scratch (allocation-free rule)
// ---------------------------------------------------------------------------
__device__ __align__(256) __nv_bfloat16 g_xh[MS*DD], g_xl[MS*DD];
__device__ __align__(256) __nv_bfloat16 g_wth[3*DD*DD], g_wtl[3*DD*DD];   // W^T concat [3N,K]
__device__ __align__(256) __nv_bfloat16 g_qh[MS*DD], g_ql[MS*DD];
__device__ __align__(256) __nv_bfloat16 g_kh[MS*DD], g_kl[MS*DD];
__device__ __align__(256) __nv_bfloat16 g_vh[MS*DD], g_vl[MS*DD];
__device__ __align__(256) __nv_bfloat16 g_vth[(size_t)BB*DD*SS], g_vtl[(size_t)BB*DD*SS];
__device__ __align__(256) float          g_p[(size_t)BB*SS*SS];
__device__ __align__(256) __nv_bfloat16 g_ph[(size_t)BB*SS*SS], g_pl[(size_t)BB*SS*SS];
__device__ __align__(256) float          g_ent[MS];

// Epilogue routing for the fused QKV projection (3 outputs, select by column)
struct ProjOut {
    const float* bias[3];
    __nv_bfloat16* oh[3];
    __nv_bfloat16* ol[3];
};

// ---------------------------------------------------------------------------
// bf16 split GEMM via mma.sync:
//   C[M,N] = (Ah+Al)[M,K] x (Bh+Bl)[N,K]^T   (3 MMAs: hh + hl + lh)
// CTA tile 128x128, K-chunk 32, 256 threads = 8 warps (4 M x 2 N),
// warp tile 32x64, 3-stage cp.async ring (prefetch 2 ahead), ONE barrier
// per chunk, 2 CTAs/SM.
// EPI 0: fp32 store. EPI 1: bf16 hi/lo split store routed via ProjOut.
// ---------------------------------------------------------------------------
template<int EPI>
__global__ __launch_bounds__(256, 2)
void mma_gemm(const __nv_bfloat16* __restrict__ Ah, const __nv_bfloat16* __restrict__ Al,
              const __nv_bfloat16* __restrict__ Bh, const __nv_bfloat16* __restrict__ Bl,
              float* __restrict__ Cf, ProjOut po,
              int N, int K, long sA, long sB, long sC)
{
    extern __shared__ char sm[];
    const uint32_t sb = smem_u32(sm);
    const int tid = threadIdx.x, lane = tid & 31, warp = tid >> 5;
    const int wm = warp & 3, wn = warp >> 2;     // 4 M-warps x 2 N-warps
    const int bz = blockIdx.z;

    const __nv_bfloat16* srcA[2] = {
        Ah + (long)bz * sA + (long)blockIdx.y * 128 * K,
        Al + (long)bz * sA + (long)blockIdx.y * 128 * K };
    const __nv_bfloat16* srcB[2] = {
        Bh + (long)bz * sB + (long)blockIdx.x * 128 * K,
        Bl + (long)bz * sB + (long)blockIdx.x * 128 * K };

    float acc[2][8][4];
    #pragma unroll
    for (int a = 0; a < 2; a++)
        #pragma unroll
        for (int b = 0; b < 8; b++)
            #pragma unroll
            for (int c = 0; c < 4; c++) acc[a][b][c] = 0.f;

    const int NC = K >> 5;

    // ---- g2s loader: per stage 128 rows x (64B hi | 64B lo) for A and B ----
    // thread u covers (row = u>>3, seg = u&7); seg 0-3 -> hi, 4-7 -> lo
    auto load_stage = [&](int c) {
        const uint32_t dstS = sb + (uint32_t)(c % NSTAGE) * STAGEB;
        const long kof = (long)c * 32;
        #pragma unroll
        for (int p = 0; p < 4; p++) {
            const int u = tid + p * 256;
            const int r = u >> 3, seg = u & 7;
            const int hl = seg >> 2;             // 0 = hi, 1 = lo
            const long so = kof + (seg & 3) * 8;
            CP16(dstS + r * ROWB + seg * 16,          srcA[hl] + (long)r * K + so);
            CP16(dstS + ATILEB + r * ROWB + seg * 16, srcB[hl] + (long)r * K + so);
        }
        CPCOMMIT();
    };

    load_stage(0);
    if (NC > 1) load_stage(1);

    for (int c = 0; c < NC; c++) {
        if (c + 2 <= NC) { CPWAIT(1); } else { CPWAIT(0); }
        __syncthreads();                          // single barrier per chunk
        if (c + 2 < NC) load_stage(c + 2);        // writes (c+2)%3 != c%3

        const uint32_t stb = sb + (uint32_t)(c % NSTAGE) * STAGEB;
        #pragma unroll
        for (int ks = 0; ks < 2; ks++) {
            // A fragments (hi+lo): 2 m16 frags, lo packed at +64B in-row
            uint32_t aHi[2][4], aLo[2][4];
            const int rA   = wm * 32 + (lane & 15);
            const int colA = ks * 32 + ((lane >> 4) << 4);
            #pragma unroll
            for (int mf = 0; mf < 2; mf++) {
                const uint32_t ad = stb + (rA + mf * 16) * ROWB + colA;
                ldsm4(aHi[mf], ad);
                ldsm4(aLo[mf], ad + 64);
            }
            // B in 4 groups of 16 rows (2 n8 frags each)
            const int rB   = wn * 64 + ((lane >> 4) & 1) * 8 + (lane & 7);
            const int colB = ks * 32 + ((lane >> 3) & 1) * 16;
            #pragma unroll
            for (int g = 0; g < 4; g++) {
                uint32_t bh4[4], bl4[4];
                const uint32_t bd = stb + ATILEB + (rB + g * 16) * ROWB + colB;
                ldsm4(bh4, bd);
                ldsm4(bl4, bd + 64);
                #pragma unroll
                for (int mf = 0; mf < 2; mf++) {
                    mma16816(acc[mf][2*g],   aHi[mf], bh4);
                    mma16816(acc[mf][2*g],   aHi[mf], bl4);
                    mma16816(acc[mf][2*g],   aLo[mf], bh4);
                    mma16816(acc[mf][2*g+1], aHi[mf], bh4 + 2);
                    mma16816(acc[mf][2*g+1], aHi[mf], bl4 + 2);
                    mma16816(acc[mf][2*g+1], aLo[mf], bh4 + 2);
                }
            }
        }
    }

    // ---- epilogue ----
    const long rbase = (long)blockIdx.y * 128 + wm * 32 + (lane >> 2);
    const int  gcol0 = blockIdx.x * 128;

    if (EPI == 0) {
        #pragma unroll
        for (int mf = 0; mf < 2; mf++)
            #pragma unroll
            for (int rh = 0; rh < 2; rh++) {
                const long r = rbase + mf * 16 + rh * 8;
                #pragma unroll
                for (int nf = 0; nf < 8; nf++) {
                    const int col = gcol0 + wn * 64 + 2 * (lane & 3) + nf * 8;
                    float2 f2;
                    f2.x = acc[mf][nf][rh * 2 + 0];
                    f2.y = acc[mf][nf][rh * 2 + 1];
                    *(float2*)(Cf + (long)bz * sC + r * N + col) = f2;
                }
            }
    } else {
        // whole 128-col tile lives in one of q/k/v (N blocks of 1024)
        const int which = gcol0 >> 10;
        const int lcol0 = gcol0 & 1023;
        const float* bias = po.bias[which];
        __nv_bfloat16* Oh = po.oh[which];
        __nv_bfloat16* Ol = po.ol[which];
        #pragma unroll
        for (int mf = 0; mf < 2; mf++)
            #pragma unroll
            for (int rh = 0; rh < 2; rh++) {
                const long r = rbase + mf * 16 + rh * 8;
                #pragma unroll
                for (int nf = 0; nf < 8; nf++) {
                    const int col = lcol0 + wn * 64 + 2 * (lane & 3) + nf * 8;
                    float v0 = acc[mf][nf][rh * 2 + 0] + bias[col];
                    float v1 = acc[mf][nf][rh * 2 + 1] + bias[col + 1];
                    __nv_bfloat16 h0 = __float2bfloat16(v0);
                    __nv_bfloat16 h1 = __float2bfloat16(v1);
                    __nv_bfloat162 hh; hh.x = h0; hh.y = h1;
                    __nv_bfloat162 ll;
                    ll.x = __float2bfloat16(v0 - __bfloat162float(h0));
                    ll.y = __float2bfloat16(v1 - __bfloat162float(h1));
                    *(__nv_bfloat162*)(Oh + r * DD + col) = hh;
                    *(__nv_bfloat162*)(Ol + r * DD + col) = ll;
                }
            }
    }
}

// ---------------------------------------------------------------------------
// fp32 -> bf16 hi/lo elementwise split (float4 vectorized)
// ---------------------------------------------------------------------------
__global__ void split_kernel(const float* __restrict__ in, __nv_bfloat16* __restrict__ oh,
                             __nv_bfloat16* __restrict__ ol, int n4)
{
    int i = blockIdx.x * 256 + threadIdx.x;
    if (i < n4) {
        float4 v = ((const float4*)in)[i];
        __nv_bfloat16 h0 = __float2bfloat16(v.x), h1 = __float2bfloat16(v.y);
        __nv_bfloat16 h2 = __float2bfloat16(v.z), h3 = __float2bfloat16(v.w);
        __nv_bfloat162 hA; hA.x = h0; hA.y = h1;
        __nv_bfloat162 hB; hB.x = h2; hB.y = h3;
        __nv_bfloat162 lA, lB;
        lA.x = __float2bfloat16(v.x - __bfloat162float(h0));
        lA.y = __float2bfloat16(v.y - __bfloat162float(h1));
        lB.x = __float2bfloat16(v.z - __bfloat162float(h2));
        lB.y = __float2bfloat16(v.w - __bfloat162float(h3));
        ((__nv_bfloat162*)oh)[2*i]   = hA;
        ((__nv_bfloat162*)oh)[2*i+1] = hB;
        ((__nv_bfloat162*)ol)[2*i]   = lA;
        ((__nv_bfloat162*)ol)[2*i+1] = lB;
    }
}

// ---------------------------------------------------------------------------
// Transpose + split fp32 [R,C] -> bf16 hi/lo [C,R] (weights)
// ---------------------------------------------------------------------------
__global__ void transpose_split(const float* __restrict__ in, __nv_bfloat16* __restrict__ oh,
                                __nv_bfloat16* __restrict__ ol, int R, int C)
{
    __shared__ float t[32][33];
    const int c0 = blockIdx.x * 32, rr0 = blockIdx.y * 32;
    const int tx = threadIdx.x, ty = threadIdx.y;
    #pragma unroll
    for (int k = 0; k < 32; k += 8)
        t[ty + k][tx] = in[(long)(rr0 + ty + k) * C + c0 + tx];
    __syncthreads();
    #pragma unroll
    for (int k = 0; k < 32; k += 8) {
        float v = t[tx][ty + k];
        __nv_bfloat16 h = __float2bfloat16(v);
        long o = (long)(c0 + ty + k) * R + rr0 + tx;
        oh[o] = h;
        ol[o] = __float2bfloat16(v - __bfloat162float(h));
    }
}

// ---------------------------------------------------------------------------
// Batched bf16-pair transpose: [R,C] hi/lo -> [C,R] hi/lo (v -> v^T)
// ---------------------------------------------------------------------------
__global__ void transpose_pair(const __nv_bfloat16* __restrict__ ih, const __nv_bfloat16* __restrict__ il,
                               __nv_bfloat16* __restrict__ oh, __nv_bfloat16* __restrict__ ol,
                               int R, int C, long sIn, long sOut)
{
    __shared__ __nv_bfloat16 th[32][34], tl[32][34];
    ih += (long)blockIdx.z * sIn;  il += (long)blockIdx.z * sIn;
    oh += (long)blockIdx.z * sOut; ol += (long)blockIdx.z * sOut;
    const int c0 = blockIdx.x * 32, rr0 = blockIdx.y * 32;
    const int tx = threadIdx.x, ty = threadIdx.y;
    #pragma unroll
    for (int k = 0; k < 32; k += 8) {
        long i = (long)(rr0 + ty + k) * C + c0 + tx;
        th[ty + k][tx] = ih[i];
        tl[ty + k][tx] = il[i];
    }
    __syncthreads();
    #pragma unroll
    for (int k = 0; k < 32; k += 8) {
        long o = (long)(c0 + ty + k) * R + rr0 + tx;
        oh[o] = th[tx][ty + k];
        ol[o] = tl[tx][ty + k];
    }
}

// ---------------------------------------------------------------------------
// Row softmax + entropy; writes probs as bf16 hi/lo (PV GEMM A operand)
// ---------------------------------------------------------------------------
__global__ void softmax_ent(const float* __restrict__ P, __nv_bfloat16* __restrict__ Ph,
                            __nv_bfloat16* __restrict__ Pl, float* __restrict__ ent,
                            const float* __restrict__ temp)
{
    __shared__ float red[256];
    const float* p = P + (long)blockIdx.x * SS;
    __nv_bfloat16* oh = Ph + (long)blockIdx.x * SS;
    __nv_bfloat16* ol = Pl + (long)blockIdx.x * SS;
    const int tid = threadIdx.x;
    const float scale = 1.0f / (8.0f * temp[0]);

    float v[8];
    #pragma unroll
    for (int j = 0; j < 8; j++) v[j] = p[tid + j * 256] * scale;

    float m = v[0];
    #pragma unroll
    for (int j = 1; j < 8; j++) m = fmaxf(m, v[j]);
    red[tid] = m; __syncthreads();
    #pragma unroll
    for (int s = 128; s > 0; s >>= 1) {
        if (tid < s) red[tid] = fmaxf(red[tid], red[tid + s]);
        __syncthreads();
    }
    m = red[0]; __syncthreads();

    float e[8], l = 0.f, t = 0.f;
    #pragma unroll
    for (int j = 0; j < 8; j++) {
        e[j] = __expf(v[j] - m);
        l += e[j];
        t += e[j] * v[j];
    }
    red[tid] = l; __syncthreads();
    #pragma unroll
    for (int s = 128; s > 0; s >>= 1) {
        if (tid < s) red[tid] += red[tid + s];
        __syncthreads();
    }
    l = red[0]; __syncthreads();
    red[tid] = t; __syncthreads();
    #pragma unroll
    for (int s = 128; s > 0; s >>= 1) {
        if (tid < s) red[tid] += red[tid + s];
        __syncthreads();
    }
    t = red[0]; __syncthreads();

    const float inv = 1.0f / l;
    #pragma unroll
    for (int j = 0; j < 8; j++) {
        float pr = e[j] * inv;
        __nv_bfloat16 h = __float2bfloat16(pr);
        oh[tid + j * 256] = h;
        ol[tid + j * 256] = __float2bfloat16(pr - __bfloat162float(h));
    }
    if (tid == 0) ent[blockIdx.x] = m + logf(l) - t * inv;
}

__global__ void ent_reduce(const float* __restrict__ ent, float* __restrict__ out)
{
    __shared__ float red[256];
    const int tid = threadIdx.x;
    float s = 0.f;
    for (int i = tid; i < MS; i += 256) s += ent[i];
    red[tid] = s; __syncthreads();
    #pragma unroll
    for (int k = 128; k > 0; k >>= 1) {
        if (tid < k) red[tid] += red[tid + k];
        __syncthreads();
    }
    if (tid == 0) out[0] = red[0] / (float)MS;
}

// ---------------------------------------------------------------------------
extern "C" void kernel_launch(void* const* d_in, const int* in_sizes, int n_in,
                              void* d_out, int out_size)
{
    const float* x    = (const float*)d_in[0];
    const float* Wq   = (const float*)d_in[1];
    const float* bq   = (const float*)d_in[2];
    const float* Wk   = (const float*)d_in[3];
    const float* bk   = (const float*)d_in[4];
    const float* Wv   = (const float*)d_in[5];
    const float* bv   = (const float*)d_in[6];
    const float* temp = (const float*)d_in[7];
    float* out = (float*)d_out;

    __nv_bfloat16 *xh, *xl, *wth, *wtl, *qh, *ql, *kh, *kl, *vh, *vl, *vth, *vtl, *pph, *ppl;
    float *p, *ent;
    cudaGetSymbolAddress((void**)&xh,  g_xh);  cudaGetSymbolAddress((void**)&xl,  g_xl);
    cudaGetSymbolAddress((void**)&wth, g_wth); cudaGetSymbolAddress((void**)&wtl, g_wtl);
    cudaGetSymbolAddress((void**)&qh,  g_qh);  cudaGetSymbolAddress((void**)&ql,  g_ql);
    cudaGetSymbolAddress((void**)&kh,  g_kh);  cudaGetSymbolAddress((void**)&kl,  g_kl);
    cudaGetSymbolAddress((void**)&vh,  g_vh);  cudaGetSymbolAddress((void**)&vl,  g_vl);
    cudaGetSymbolAddress((void**)&vth, g_vth); cudaGetSymbolAddress((void**)&vtl, g_vtl);
    cudaGetSymbolAddress((void**)&p,   g_p);
    cudaGetSymbolAddress((void**)&pph, g_ph);  cudaGetSymbolAddress((void**)&ppl, g_pl);
    cudaGetSymbolAddress((void**)&ent, g_ent);

    cudaFuncSetAttribute(mma_gemm<0>, cudaFuncAttributeMaxDynamicSharedMemorySize, SMEMB);
    cudaFuncSetAttribute(mma_gemm<1>, cudaFuncAttributeMaxDynamicSharedMemorySize, SMEMB);

    ProjOut poNull = {};

    // 1) Split x; transpose+split weights into concat W^T [3*D, D]
    split_kernel<<<(MS*DD/4 + 255) / 256, 256>>>(x, xh, xl, MS*DD/4);
    {
        dim3 blk(32, 8);
        dim3 grd(DD / 32, DD / 32, 1);
        transpose_split<<<grd, blk>>>(Wq, wth + 0*DD*DD, wtl + 0*DD*DD, DD, DD);
        transpose_split<<<grd, blk>>>(Wk, wth + 1*DD*DD, wtl + 1*DD*DD, DD, DD);
        transpose_split<<<grd, blk>>>(Wv, wth + 2*DD*DD, wtl + 2*DD*DD, DD, DD);
    }
    // 2) Fused QKV projection: M=8192, N=3072, K=1024 -> bf16 hi/lo outputs
    {
        ProjOut po;
        po.bias[0] = bq; po.bias[1] = bk; po.bias[2] = bv;
        po.oh[0] = qh; po.oh[1] = kh; po.oh[2] = vh;
        po.ol[0] = ql; po.ol[1] = kl; po.ol[2] = vl;
        dim3 grd(3*DD / 128, MS / 128, 1);
        mma_gemm<1><<<grd, 256, SMEMB>>>(xh, xl, wth, wtl, nullptr, po, 3*DD, DD, 0, 0, 0);
    }
    // 3) v -> v^T hi/lo per batch ([S,D] -> [D,S])
    {
        dim3 blk(32, 8);
        dim3 grd(DD / 32, SS / 32, BB);
        transpose_pair<<<grd, blk>>>(vh, vl, vth, vtl, SS, DD, (long)SS * DD, (long)DD * SS);
    }
    // 4) Scores (per batch: 2048x2048, K=1024), unscaled fp32
    {
        dim3 grd(SS / 128, SS / 128, BB);
        mma_gemm<0><<<grd, 256, SMEMB>>>(qh, ql, kh, kl, p, poNull,
                                         SS, DD, (long)SS*DD, (long)SS*DD, (long)SS*SS);
    }
    // 5) Softmax + entropy; probs -> bf16 hi/lo
    softmax_ent<<<MS, 256>>>(p, pph, ppl, ent, temp);
    // 6) PV (per batch: 2048x1024, K=2048) -> out fp32
    {
        dim3 grd(DD / 128, SS / 128, BB);
        mma_gemm<0><<<grd, 256, SMEMB>>>(pph, ppl, vth, vtl, out, poNull,
                                         DD, SS, (long)SS*SS, (long)DD*SS, (long)SS*DD);
    }
    // 7) Entropy mean scalar
    ent_reduce<<<1, 256>>>(ent, out + OUT_ELEMS);
}

// round 8
// speedup vs baseline: 1.3961x; 1.2091x over previous
#include <cuda_runtime.h>
#include <cuda_bf16.h>
#include <cuda_fp16.h>
#include <math.h>
#include <stdint.h>

// Problem dims (fixed)
#define BB 4
#define SS 2048
#define DD 1024
#define MS (BB*SS)          // 8192 rows total
#define OUT_ELEMS (MS*DD)

// --- bf16 split GEMM smem geometry: rows hold hi(64B)|lo(64B), stride 144B ---
#define ROWB   144
#define ATILEB (128*ROWB)
#define STAGEB (2*ATILEB)              // A + B tile = 36864 B
#define NSTAGE 3
#define SMEMB  (NSTAGE*STAGEB)         // 110592 B -> 2 CTAs/SM

// --- fp16 single GEMM smem geometry: rows 64B data + 16B pad -> 80B ---
#define ROWB2   80
#define ATIL2   (128*ROWB2)
#define STAGE2  (2*ATIL2)              // 20480 B
#define SMEM2   (NSTAGE*STAGE2)        // 61440 B -> 2 CTAs/SM easily

// ---------------------------------------------------------------------------
// PTX helpers (sm_80-level only: cp.async, ldmatrix, mma.sync)
// ---------------------------------------------------------------------------
__device__ __forceinline__ uint32_t smem_u32(const void* p) {
    uint32_t a;
    asm("{ .reg .u64 t; cvta.to.shared.u64 t, %1; cvt.u32.u64 %0, t; }" : "=r"(a) : "l"(p));
    return a;
}
#define CP16(d, s) asm volatile("cp.async.cg.shared.global [%0], [%1], 16;" :: "r"(d), "l"(s))
#define CPCOMMIT() asm volatile("cp.async.commit_group;" ::: "memory")
#define CPWAIT(n)  asm volatile("cp.async.wait_group %0;" :: "n"(n) : "memory")

__device__ __forceinline__ void ldsm4(uint32_t* r, uint32_t a) {
    asm volatile("ldmatrix.sync.aligned.m8n8.x4.shared.b16 {%0,%1,%2,%3}, [%4];"
                 : "=r"(r[0]), "=r"(r[1]), "=r"(r[2]), "=r"(r[3]) : "r"(a));
}
__device__ __forceinline__ void mma16816(float* c, const uint32_t* a, const uint32_t* b) {
    asm volatile("mma.sync.aligned.m16n8k16.row.col.f32.bf16.bf16.f32 "
                 "{%0,%1,%2,%3}, {%4,%5,%6,%7}, {%8,%9}, {%0,%1,%2,%3};"
                 : "+f"(c[0]), "+f"(c[1]), "+f"(c[2]), "+f"(c[3])
                 : "r"(a[0]), "r"(a[1]), "r"(a[2]), "r"(a[3]), "r"(b[0]), "r"(b[1]));
}
__device__ __forceinline__ void mma16816h(float* c, const uint32_t* a, const uint32_t* b) {
    asm volatile("mma.sync.aligned.m16n8k16.row.col.f32.f16.f16.f32 "
                 "{%0,%1,%2,%3}, {%4,%5,%6,%7}, {%8,%9}, {%0,%1,%2,%3};"
                 : "+f"(c[0]), "+f"(c[1]), "+f"(c[2]), "+f"(c[3])
                 : "r"(a[0]), "r"(a[1]), "r"(a[2]), "r"(a[3]), "r"(b[0]), "r"(b[1]));
}

// ---------------------------------------------------------------------------
// Static scratch (allocation-free rule)
// ---------------------------------------------------------------------------
__device__ __align__(256) __nv_bfloat16 g_xh[MS*DD], g_xl[MS*DD];
__device__ __align__(256) __nv_bfloat16 g_wth[3*DD*DD], g_wtl[3*DD*DD];   // W^T concat [3N,K]
__device__ __align__(256) __nv_bfloat16 g_qh[MS*DD], g_ql[MS*DD];
__device__ __align__(256) __nv_bfloat16 g_kh[MS*DD], g_kl[MS*DD];
__device__ __align__(256) __half         g_v16[MS*DD];                    // v fp16 [S,D] per batch
__device__ __align__(256) __half         g_vt16[(size_t)BB*DD*SS];        // v^T fp16 [D,S] per batch
__device__ __align__(256) float          g_p[(size_t)BB*SS*SS];
__device__ __align__(256) __half         g_p16[(size_t)BB*SS*SS];
__device__ __align__(256) float          g_ent[MS];

// Epilogue routing for the fused QKV projection: q,k -> bf16 hi/lo; v -> fp16
struct ProjOut {
    const float* bias[3];
    __nv_bfloat16* oh[2];
    __nv_bfloat16* ol[2];
    __half* o16;
};

// ---------------------------------------------------------------------------
// bf16 split GEMM via mma.sync:
//   C[M,N] = (Ah+Al)[M,K] x (Bh+Bl)[N,K]^T   (3 MMAs: hh + hl + lh)
// CTA tile 128x128, K-chunk 32, 256 threads = 8 warps (4 M x 2 N),
// warp tile 32x64, 3-stage cp.async ring, ONE barrier/chunk, 2 CTAs/SM.
// EPI 0: fp32 store. EPI 1: q/k bf16 hi/lo + v fp16 via ProjOut.
// ---------------------------------------------------------------------------
template<int EPI>
__global__ __launch_bounds__(256, 2)
void mma_gemm(const __nv_bfloat16* __restrict__ Ah, const __nv_bfloat16* __restrict__ Al,
              const __nv_bfloat16* __restrict__ Bh, const __nv_bfloat16* __restrict__ Bl,
              float* __restrict__ Cf, ProjOut po,
              int N, int K, long sA, long sB, long sC)
{
    extern __shared__ char sm[];
    const uint32_t sb = smem_u32(sm);
    const int tid = threadIdx.x, lane = tid & 31, warp = tid >> 5;
    const int wm = warp & 3, wn = warp >> 2;     // 4 M-warps x 2 N-warps
    const int bz = blockIdx.z;

    const __nv_bfloat16* srcA[2] = {
        Ah + (long)bz * sA + (long)blockIdx.y * 128 * K,
        Al + (long)bz * sA + (long)blockIdx.y * 128 * K };
    const __nv_bfloat16* srcB[2] = {
        Bh + (long)bz * sB + (long)blockIdx.x * 128 * K,
        Bl + (long)bz * sB + (long)blockIdx.x * 128 * K };

    float acc[2][8][4];
    #pragma unroll
    for (int a = 0; a < 2; a++)
        #pragma unroll
        for (int b = 0; b < 8; b++)
            #pragma unroll
            for (int c = 0; c < 4; c++) acc[a][b][c] = 0.f;

    const int NC = K >> 5;

    auto load_stage = [&](int c) {
        const uint32_t dstS = sb + (uint32_t)(c % NSTAGE) * STAGEB;
        const long kof = (long)c * 32;
        #pragma unroll
        for (int p = 0; p < 4; p++) {
            const int u = tid + p * 256;
            const int r = u >> 3, seg = u & 7;
            const int hl = seg >> 2;             // 0 = hi, 1 = lo
            const long so = kof + (seg & 3) * 8;
            CP16(dstS + r * ROWB + seg * 16,          srcA[hl] + (long)r * K + so);
            CP16(dstS + ATILEB + r * ROWB + seg * 16, srcB[hl] + (long)r * K + so);
        }
        CPCOMMIT();
    };

    load_stage(0);
    if (NC > 1) load_stage(1);

    for (int c = 0; c < NC; c++) {
        if (c + 2 <= NC) { CPWAIT(1); } else { CPWAIT(0); }
        __syncthreads();
        if (c + 2 < NC) load_stage(c + 2);

        const uint32_t stb = sb + (uint32_t)(c % NSTAGE) * STAGEB;
        #pragma unroll
        for (int ks = 0; ks < 2; ks++) {
            uint32_t aHi[2][4], aLo[2][4];
            const int rA   = wm * 32 + (lane & 15);
            const int colA = ks * 32 + ((lane >> 4) << 4);
            #pragma unroll
            for (int mf = 0; mf < 2; mf++) {
                const uint32_t ad = stb + (rA + mf * 16) * ROWB + colA;
                ldsm4(aHi[mf], ad);
                ldsm4(aLo[mf], ad + 64);
            }
            const int rB   = wn * 64 + ((lane >> 4) & 1) * 8 + (lane & 7);
            const int colB = ks * 32 + ((lane >> 3) & 1) * 16;
            #pragma unroll
            for (int g = 0; g < 4; g++) {
                uint32_t bh4[4], bl4[4];
                const uint32_t bd = stb + ATILEB + (rB + g * 16) * ROWB + colB;
                ldsm4(bh4, bd);
                ldsm4(bl4, bd + 64);
                #pragma unroll
                for (int mf = 0; mf < 2; mf++) {
                    mma16816(acc[mf][2*g],   aHi[mf], bh4);
                    mma16816(acc[mf][2*g],   aHi[mf], bl4);
                    mma16816(acc[mf][2*g],   aLo[mf], bh4);
                    mma16816(acc[mf][2*g+1], aHi[mf], bh4 + 2);
                    mma16816(acc[mf][2*g+1], aHi[mf], bl4 + 2);
                    mma16816(acc[mf][2*g+1], aLo[mf], bh4 + 2);
                }
            }
        }
    }

    // ---- epilogue ----
    const long rbase = (long)blockIdx.y * 128 + wm * 32 + (lane >> 2);
    const int  gcol0 = blockIdx.x * 128;

    if (EPI == 0) {
        #pragma unroll
        for (int mf = 0; mf < 2; mf++)
            #pragma unroll
            for (int rh = 0; rh < 2; rh++) {
                const long r = rbase + mf * 16 + rh * 8;
                #pragma unroll
                for (int nf = 0; nf < 8; nf++) {
                    const int col = gcol0 + wn * 64 + 2 * (lane & 3) + nf * 8;
                    float2 f2;
                    f2.x = acc[mf][nf][rh * 2 + 0];
                    f2.y = acc[mf][nf][rh * 2 + 1];
                    *(float2*)(Cf + (long)bz * sC + r * N + col) = f2;
                }
            }
    } else {
        const int which = gcol0 >> 10;           // 0=q, 1=k, 2=v
        const int lcol0 = gcol0 & 1023;
        const float* bias = po.bias[which];
        if (which < 2) {
            __nv_bfloat16* Oh = po.oh[which];
            __nv_bfloat16* Ol = po.ol[which];
            #pragma unroll
            for (int mf = 0; mf < 2; mf++)
                #pragma unroll
                for (int rh = 0; rh < 2; rh++) {
                    const long r = rbase + mf * 16 + rh * 8;
                    #pragma unroll
                    for (int nf = 0; nf < 8; nf++) {
                        const int col = lcol0 + wn * 64 + 2 * (lane & 3) + nf * 8;
                        float v0 = acc[mf][nf][rh * 2 + 0] + bias[col];
                        float v1 = acc[mf][nf][rh * 2 + 1] + bias[col + 1];
                        __nv_bfloat16 h0 = __float2bfloat16(v0);
                        __nv_bfloat16 h1 = __float2bfloat16(v1);
                        __nv_bfloat162 hh; hh.x = h0; hh.y = h1;
                        __nv_bfloat162 ll;
                        ll.x = __float2bfloat16(v0 - __bfloat162float(h0));
                        ll.y = __float2bfloat16(v1 - __bfloat162float(h1));
                        *(__nv_bfloat162*)(Oh + r * DD + col) = hh;
                        *(__nv_bfloat162*)(Ol + r * DD + col) = ll;
                    }
                }
        } else {
            __half* O = po.o16;
            #pragma unroll
            for (int mf = 0; mf < 2; mf++)
                #pragma unroll
                for (int rh = 0; rh < 2; rh++) {
                    const long r = rbase + mf * 16 + rh * 8;
                    #pragma unroll
                    for (int nf = 0; nf < 8; nf++) {
                        const int col = lcol0 + wn * 64 + 2 * (lane & 3) + nf * 8;
                        float v0 = acc[mf][nf][rh * 2 + 0] + bias[col];
                        float v1 = acc[mf][nf][rh * 2 + 1] + bias[col + 1];
                        __half2 hv; hv.x = __float2half(v0); hv.y = __float2half(v1);
                        *(__half2*)(O + r * DD + col) = hv;
                    }
                }
        }
    }
}

// ---------------------------------------------------------------------------
// fp16 single-term GEMM: C[M,N] = A[M,K] x B[N,K]^T, fp32 accum/store.
// Same tiling as above, 1 MMA per frag pair. Used for PV.
// ---------------------------------------------------------------------------
__global__ __launch_bounds__(256, 2)
void mma_gemm_h1(const __half* __restrict__ A, const __half* __restrict__ B,
                 float* __restrict__ Cf, int N, int K, long sA, long sB, long sC)
{
    extern __shared__ char sm[];
    const uint32_t sb = smem_u32(sm);
    const int tid = threadIdx.x, lane = tid & 31, warp = tid >> 5;
    const int wm = warp & 3, wn = warp >> 2;
    const int bz = blockIdx.z;

    const __half* srcA = A + (long)bz * sA + (long)blockIdx.y * 128 * K;
    const __half* srcB = B + (long)bz * sB + (long)blockIdx.x * 128 * K;

    float acc[2][8][4];
    #pragma unroll
    for (int a = 0; a < 2; a++)
        #pragma unroll
        for (int b = 0; b < 8; b++)
            #pragma unroll
            for (int c = 0; c < 4; c++) acc[a][b][c] = 0.f;

    const int NC = K >> 5;

    auto load_stage = [&](int c) {
        const uint32_t dstS = sb + (uint32_t)(c % NSTAGE) * STAGE2;
        const long kof = (long)c * 32;
        #pragma unroll
        for (int p = 0; p < 2; p++) {
            const int u = tid + p * 256;
            const int r = u >> 2, s = u & 3;
            const long so = kof + s * 8;
            CP16(dstS + r * ROWB2 + s * 16,         srcA + (long)r * K + so);
            CP16(dstS + ATIL2 + r * ROWB2 + s * 16, srcB + (long)r * K + so);
        }
        CPCOMMIT();
    };

    load_stage(0);
    if (NC > 1) load_stage(1);

    for (int c = 0; c < NC; c++) {
        if (c + 2 <= NC) { CPWAIT(1); } else { CPWAIT(0); }
        __syncthreads();
        if (c + 2 < NC) load_stage(c + 2);

        const uint32_t stb = sb + (uint32_t)(c % NSTAGE) * STAGE2;
        #pragma unroll
        for (int ks = 0; ks < 2; ks++) {
            uint32_t aF[2][4];
            const int rA   = wm * 32 + (lane & 15);
            const int colA = ks * 32 + ((lane >> 4) << 4);
            #pragma unroll
            for (int mf = 0; mf < 2; mf++)
                ldsm4(aF[mf], stb + (rA + mf * 16) * ROWB2 + colA);
            const int rB   = wn * 64 + ((lane >> 4) & 1) * 8 + (lane & 7);
            const int colB = ks * 32 + ((lane >> 3) & 1) * 16;
            #pragma unroll
            for (int g = 0; g < 4; g++) {
                uint32_t b4[4];
                ldsm4(b4, stb + ATIL2 + (rB + g * 16) * ROWB2 + colB);
                #pragma unroll
                for (int mf = 0; mf < 2; mf++) {
                    mma16816h(acc[mf][2*g],   aF[mf], b4);
                    mma16816h(acc[mf][2*g+1], aF[mf], b4 + 2);
                }
            }
        }
    }

    const long rbase = (long)blockIdx.y * 128 + wm * 32 + (lane >> 2);
    const int  gcol0 = blockIdx.x * 128;
    #pragma unroll
    for (int mf = 0; mf < 2; mf++)
        #pragma unroll
        for (int rh = 0; rh < 2; rh++) {
            const long r = rbase + mf * 16 + rh * 8;
            #pragma unroll
            for (int nf = 0; nf < 8; nf++) {
                const int col = gcol0 + wn * 64 + 2 * (lane & 3) + nf * 8;
                float2 f2;
                f2.x = acc[mf][nf][rh * 2 + 0];
                f2.y = acc[mf][nf][rh * 2 + 1];
                *(float2*)(Cf + (long)bz * sC + r * N + col) = f2;
            }
        }
}

// ---------------------------------------------------------------------------
// fp32 -> bf16 hi/lo elementwise split (float4 vectorized)
// ---------------------------------------------------------------------------
__global__ void split_kernel(const float* __restrict__ in, __nv_bfloat16* __restrict__ oh,
                             __nv_bfloat16* __restrict__ ol, int n4)
{
    int i = blockIdx.x * 256 + threadIdx.x;
    if (i < n4) {
        float4 v = ((const float4*)in)[i];
        __nv_bfloat16 h0 = __float2bfloat16(v.x), h1 = __float2bfloat16(v.y);
        __nv_bfloat16 h2 = __float2bfloat16(v.z), h3 = __float2bfloat16(v.w);
        __nv_bfloat162 hA; hA.x = h0; hA.y = h1;
        __nv_bfloat162 hB; hB.x = h2; hB.y = h3;
        __nv_bfloat162 lA, lB;
        lA.x = __float2bfloat16(v.x - __bfloat162float(h0));
        lA.y = __float2bfloat16(v.y - __bfloat162float(h1));
        lB.x = __float2bfloat16(v.z - __bfloat162float(h2));
        lB.y = __float2bfloat16(v.w - __bfloat162float(h3));
        ((__nv_bfloat162*)oh)[2*i]   = hA;
        ((__nv_bfloat162*)oh)[2*i+1] = hB;
        ((__nv_bfloat162*)ol)[2*i]   = lA;
        ((__nv_bfloat162*)ol)[2*i+1] = lB;
    }
}

// ---------------------------------------------------------------------------
// Transpose + split fp32 [R,C] -> bf16 hi/lo [C,R] (weights)
// ---------------------------------------------------------------------------
__global__ void transpose_split(const float* __restrict__ in, __nv_bfloat16* __restrict__ oh,
                                __nv_bfloat16* __restrict__ ol, int R, int C)
{
    __shared__ float t[32][33];
    const int c0 = blockIdx.x * 32, rr0 = blockIdx.y * 32;
    const int tx = threadIdx.x, ty = threadIdx.y;
    #pragma unroll
    for (int k = 0; k < 32; k += 8)
        t[ty + k][tx] = in[(long)(rr0 + ty + k) * C + c0 + tx];
    __syncthreads();
    #pragma unroll
    for (int k = 0; k < 32; k += 8) {
        float v = t[tx][ty + k];
        __nv_bfloat16 h = __float2bfloat16(v);
        long o = (long)(c0 + ty + k) * R + rr0 + tx;
        oh[o] = h;
        ol[o] = __float2bfloat16(v - __bfloat162float(h));
    }
}

// ---------------------------------------------------------------------------
// Batched fp16 transpose: [R,C] -> [C,R]  (v -> v^T)
// ---------------------------------------------------------------------------
__global__ void transpose_h(const __half* __restrict__ in, __half* __restrict__ out,
                            int R, int C, long sIn, long sOut)
{
    __shared__ __half t[32][34];
    in  += (long)blockIdx.z * sIn;
    out += (long)blockIdx.z * sOut;
    const int c0 = blockIdx.x * 32, rr0 = blockIdx.y * 32;
    const int tx = threadIdx.x, ty = threadIdx.y;
    #pragma unroll
    for (int k = 0; k < 32; k += 8)
        t[ty + k][tx] = in[(long)(rr0 + ty + k) * C + c0 + tx];
    __syncthreads();
    #pragma unroll
    for (int k = 0; k < 32; k += 8)
        out[(long)(c0 + ty + k) * R + rr0 + tx] = t[tx][ty + k];
}

// ---------------------------------------------------------------------------
// Row softmax + entropy; writes probs as fp16 (PV GEMM A operand)
// ---------------------------------------------------------------------------
__global__ void softmax_ent(const float* __restrict__ P, __half* __restrict__ P16,
                            float* __restrict__ ent, const float* __restrict__ temp)
{
    __shared__ float red[256];
    const float* p = P + (long)blockIdx.x * SS;
    __half* o = P16 + (long)blockIdx.x * SS;
    const int tid = threadIdx.x;
    const float scale = 1.0f / (8.0f * temp[0]);

    float v[8];
    #pragma unroll
    for (int j = 0; j < 8; j++) v[j] = p[tid + j * 256] * scale;

    float m = v[0];
    #pragma unroll
    for (int j = 1; j < 8; j++) m = fmaxf(m, v[j]);
    red[tid] = m; __syncthreads();
    #pragma unroll
    for (int s = 128; s > 0; s >>= 1) {
        if (tid < s) red[tid] = fmaxf(red[tid], red[tid + s]);
        __syncthreads();
    }
    m = red[0]; __syncthreads();

    float e[8], l = 0.f, t = 0.f;
    #pragma unroll
    for (int j = 0; j < 8; j++) {
        e[j] = __expf(v[j] - m);
        l += e[j];
        t += e[j] * v[j];
    }
    red[tid] = l; __syncthreads();
    #pragma unroll
    for (int s = 128; s > 0; s >>= 1) {
        if (tid < s) red[tid] += red[tid + s];
        __syncthreads();
    }
    l = red[0]; __syncthreads();
    red[tid] = t; __syncthreads();
    #pragma unroll
    for (int s = 128; s > 0; s >>= 1) {
        if (tid < s) red[tid] += red[tid + s];
        __syncthreads();
    }
    t = red[0]; __syncthreads();

    const float inv = 1.0f / l;
    #pragma unroll
    for (int j = 0; j < 8; j++)
        o[tid + j * 256] = __float2half(e[j] * inv);

    if (tid == 0) ent[blockIdx.x] = m + logf(l) - t * inv;
}

__global__ void ent_reduce(const float* __restrict__ ent, float* __restrict__ out)
{
    __shared__ float red[256];
    const int tid = threadIdx.x;
    float s = 0.f;
    for (int i = tid; i < MS; i += 256) s += ent[i];
    red[tid] = s; __syncthreads();
    #pragma unroll
    for (int k = 128; k > 0; k >>= 1) {
        if (tid < k) red[tid] += red[tid + k];
        __syncthreads();
    }
    if (tid == 0) out[0] = red[0] / (float)MS;
}

// ---------------------------------------------------------------------------
extern "C" void kernel_launch(void* const* d_in, const int* in_sizes, int n_in,
                              void* d_out, int out_size)
{
    const float* x    = (const float*)d_in[0];
    const float* Wq   = (const float*)d_in[1];
    const float* bq   = (const float*)d_in[2];
    const float* Wk   = (const float*)d_in[3];
    const float* bk   = (const float*)d_in[4];
    const float* Wv   = (const float*)d_in[5];
    const float* bv   = (const float*)d_in[6];
    const float* temp = (const float*)d_in[7];
    float* out = (float*)d_out;

    __nv_bfloat16 *xh, *xl, *wth, *wtl, *qh, *ql, *kh, *kl;
    __half *v16, *vt16, *p16;
    float *p, *ent;
    cudaGetSymbolAddress((void**)&xh,  g_xh);  cudaGetSymbolAddress((void**)&xl,  g_xl);
    cudaGetSymbolAddress((void**)&wth, g_wth); cudaGetSymbolAddress((void**)&wtl, g_wtl);
    cudaGetSymbolAddress((void**)&qh,  g_qh);  cudaGetSymbolAddress((void**)&ql,  g_ql);
    cudaGetSymbolAddress((void**)&kh,  g_kh);  cudaGetSymbolAddress((void**)&kl,  g_kl);
    cudaGetSymbolAddress((void**)&v16, g_v16); cudaGetSymbolAddress((void**)&vt16, g_vt16);
    cudaGetSymbolAddress((void**)&p,   g_p);   cudaGetSymbolAddress((void**)&p16, g_p16);
    cudaGetSymbolAddress((void**)&ent, g_ent);

    cudaFuncSetAttribute(mma_gemm<0>, cudaFuncAttributeMaxDynamicSharedMemorySize, SMEMB);
    cudaFuncSetAttribute(mma_gemm<1>, cudaFuncAttributeMaxDynamicSharedMemorySize, SMEMB);
    cudaFuncSetAttribute(mma_gemm_h1, cudaFuncAttributeMaxDynamicSharedMemorySize, SMEM2);

    ProjOut poNull = {};

    // 1) Split x; transpose+split weights into concat W^T [3*D, D]
    split_kernel<<<(MS*DD/4 + 255) / 256, 256>>>(x, xh, xl, MS*DD/4);
    {
        dim3 blk(32, 8);
        dim3 grd(DD / 32, DD / 32, 1);
        transpose_split<<<grd, blk>>>(Wq, wth + 0*DD*DD, wtl + 0*DD*DD, DD, DD);
        transpose_split<<<grd, blk>>>(Wk, wth + 1*DD*DD, wtl + 1*DD*DD, DD, DD);
        transpose_split<<<grd, blk>>>(Wv, wth + 2*DD*DD, wtl + 2*DD*DD, DD, DD);
    }
    // 2) Fused QKV projection: q,k -> bf16 hi/lo; v -> fp16
    {
        ProjOut po;
        po.bias[0] = bq; po.bias[1] = bk; po.bias[2] = bv;
        po.oh[0] = qh; po.oh[1] = kh;
        po.ol[0] = ql; po.ol[1] = kl;
        po.o16 = v16;
        dim3 grd(3*DD / 128, MS / 128, 1);
        mma_gemm<1><<<grd, 256, SMEMB>>>(xh, xl, wth, wtl, nullptr, po, 3*DD, DD, 0, 0, 0);
    }
    // 3) v -> v^T fp16 per batch ([S,D] -> [D,S])
    {
        dim3 blk(32, 8);
        dim3 grd(DD / 32, SS / 32, BB);
        transpose_h<<<grd, blk>>>(v16, vt16, SS, DD, (long)SS * DD, (long)DD * SS);
    }
    // 4) Scores (per batch: 2048x2048, K=1024), unscaled fp32, bf16 3-term
    {
        dim3 grd(SS / 128, SS / 128, BB);
        mma_gemm<0><<<grd, 256, SMEMB>>>(qh, ql, kh, kl, p, poNull,
                                         SS, DD, (long)SS*DD, (long)SS*DD, (long)SS*SS);
    }
    // 5) Softmax + entropy; probs -> fp16
    softmax_ent<<<MS, 256>>>(p, p16, ent, temp);
    // 6) PV (per batch: 2048x1024, K=2048), single fp16 MMA -> out fp32
    {
        dim3 grd(DD / 128, SS / 128, BB);
        mma_gemm_h1<<<grd, 256, SMEM2>>>(p16, vt16, out,
                                         DD, SS, (long)SS*SS, (long)DD*SS, (long)SS*DD);
    }
    // 7) Entropy mean scalar
    ent_reduce<<<1, 256>>>(ent, out + OUT_ELEMS);
}